// round 9
// baseline (speedup 1.0000x reference)
#include <cuda_runtime.h>
#include <math.h>
#include <stdint.h>

// Problem constants
#define BB   2
#define SS   2048
#define DDIM 1024
#define HH   16
#define DK   64
#define FFD  4096
#define MTOT (BB*SS)   // 4096 rows

// ---------------------------------------------------------------------------
// Scratch buffers (device globals; no runtime allocation allowed)
// ---------------------------------------------------------------------------
__device__ float g_xn [MTOT*DDIM];
__device__ float g_q  [MTOT*DDIM];
__device__ float g_k  [MTOT*DDIM];
__device__ float g_v  [MTOT*DDIM];
__device__ float g_ctx[MTOT*DDIM];
__device__ float g_h  [MTOT*DDIM];
__device__ float g_hn [MTOT*DDIM];
__device__ float g_ff [MTOT*FFD];

// ---------------------------------------------------------------------------
// LayerNorm (faithful: unbiased std, denom = sqrt(std + eps))
// ---------------------------------------------------------------------------
__global__ __launch_bounds__(256) void ln_kernel(
    const float* __restrict__ x, const float* __restrict__ alpha,
    const float* __restrict__ beta, float* __restrict__ y)
{
    const int row = blockIdx.x;
    const float4* xr = reinterpret_cast<const float4*>(x + (size_t)row * DDIM);
    float4 vv = xr[threadIdx.x];
    float s  = vv.x + vv.y + vv.z + vv.w;
    float s2 = vv.x*vv.x + vv.y*vv.y + vv.z*vv.z + vv.w*vv.w;

    __shared__ float red0[8], red1[8];
    #pragma unroll
    for (int o = 16; o; o >>= 1) {
        s  += __shfl_xor_sync(0xffffffffu, s,  o);
        s2 += __shfl_xor_sync(0xffffffffu, s2, o);
    }
    const int warp = threadIdx.x >> 5, lane = threadIdx.x & 31;
    if (lane == 0) { red0[warp] = s; red1[warp] = s2; }
    __syncthreads();
    if (threadIdx.x == 0) {
        float t = 0.f, t2 = 0.f;
        #pragma unroll
        for (int i = 0; i < 8; i++) { t += red0[i]; t2 += red1[i]; }
        red0[0] = t; red1[0] = t2;
    }
    __syncthreads();
    s = red0[0]; s2 = red1[0];

    const float mean = s * (1.0f / DDIM);
    const float var  = fmaxf(0.f, (s2 - s * mean) * (1.0f / (DDIM - 1)));  // unbiased
    const float stdv = sqrtf(var);
    const float inv  = 1.0f / sqrtf(stdv + 1e-6f);   // sqrt(std + eps) !
    const float a0 = alpha[0], b0 = beta[0];

    float4 o;
    o.x = a0 * (vv.x - mean) * inv + b0;
    o.y = a0 * (vv.y - mean) * inv + b0;
    o.z = a0 * (vv.z - mean) * inv + b0;
    o.w = a0 * (vv.w - mean) * inv + b0;
    reinterpret_cast<float4*>(y + (size_t)row * DDIM)[threadIdx.x] = o;
}

// ---------------------------------------------------------------------------
// tf32 helpers
// ---------------------------------------------------------------------------
__device__ __forceinline__ uint32_t f2tf32(float x) {
    uint32_t r;
    asm("cvt.rna.tf32.f32 %0, %1;" : "=r"(r) : "f"(x));
    return r;
}

__device__ __forceinline__ void mma_tf32(
    float c[4], const uint32_t a[4], const uint32_t b[2])
{
    asm volatile(
        "mma.sync.aligned.m16n8k8.row.col.f32.tf32.tf32.f32 "
        "{%0,%1,%2,%3}, {%4,%5,%6,%7}, {%8,%9}, {%0,%1,%2,%3};\n"
        : "+f"(c[0]), "+f"(c[1]), "+f"(c[2]), "+f"(c[3])
        : "r"(a[0]), "r"(a[1]), "r"(a[2]), "r"(a[3]), "r"(b[0]), "r"(b[1]));
}

// ---------------------------------------------------------------------------
// Tensor-core GEMM (NT), software-pipelined:
//   C[M,N] = A[M,K]*W[N,K]^T + bias (+relu) (+res)
// 512 threads, warp grid 4(m)x4(n), warp tile 32x32 (2x4 m16n8k8 frags).
// 2-stage smem double buffer (fragment-major layouts from round 7), global
// prefetch into registers overlapped with the MMA phase. K-tile 32.
// Dynamic smem: 2 * (32*132 + 64*66) u32 = 67584 bytes.
// ---------------------------------------------------------------------------
#define GEMM_STAGE_U32 (32*132 + 64*66)   // 8448
#define GEMM_SMEM_BYTES (2 * GEMM_STAGE_U32 * 4)

__global__ __launch_bounds__(512, 1) void gemm_tc(
    const float* __restrict__ A, const float* __restrict__ W,
    const float* __restrict__ bias, const float* __restrict__ res,
    float* __restrict__ C, int M, int N, int K, int relu)
{
    extern __shared__ uint32_t sm[];

    const int tid  = threadIdx.x;
    const int lane = tid & 31;
    const int warp = tid >> 5;          // 0..15
    const int wm = warp >> 2;           // 0..3
    const int wn = warp & 3;            // 0..3
    const int g  = lane >> 2;           // 0..7
    const int t  = lane & 3;            // 0..3
    const int m0 = blockIdx.y * 128, n0 = blockIdx.x * 128;

    // per-thread fill-slot decomposition (2 A slots + 2 B slots)
    int rS[2], kqS[2];
    #pragma unroll
    for (int u = 0; u < 2; u++) {
        const int f = tid + u * 512;    // 0..1023
        rS[u]  = f >> 3;                // 0..127
        kqS[u] = (f & 7) << 2;          // 0..28 step 4
    }

    float acc[2][4][4];
    #pragma unroll
    for (int i = 0; i < 2; i++)
        #pragma unroll
        for (int j = 0; j < 4; j++)
            #pragma unroll
            for (int p = 0; p < 4; p++) acc[i][j][p] = 0.f;

    float4 pa[2], pb[2];

    // ---- prologue: load tile 0, fill stage 0 ----
    #pragma unroll
    for (int u = 0; u < 2; u++) {
        pa[u] = *reinterpret_cast<const float4*>(A + (size_t)(m0 + rS[u]) * K + kqS[u]);
        pb[u] = *reinterpret_cast<const float4*>(W + (size_t)(n0 + rS[u]) * K + kqS[u]);
    }
    {
        uint32_t* As = sm;
        uint32_t* Bs = sm + 32*132;
        #pragma unroll
        for (int u = 0; u < 2; u++) {
            const int r = rS[u], kq = kqS[u];
            const int kc = kq >> 3, lo = (kq >> 2) & 1;
            {   // A
                const int mf = r >> 4, gg = r & 7, hi = (r >> 3) & 1;
                uint32_t* d = As + (mf*4 + kc) * 132 + gg*16 + (hi + 2*lo);
                d[0]  = f2tf32(pa[u].x); d[4]  = f2tf32(pa[u].y);
                d[8]  = f2tf32(pa[u].z); d[12] = f2tf32(pa[u].w);
            }
            {   // B
                const int nf = r >> 3, gp = r & 7;
                uint32_t* d = Bs + (nf*4 + kc) * 66 + gp*8 + lo;
                d[0] = f2tf32(pb[u].x); d[2] = f2tf32(pb[u].y);
                d[4] = f2tf32(pb[u].z); d[6] = f2tf32(pb[u].w);
            }
        }
    }
    __syncthreads();

    int cur = 0;
    for (int k0 = 0; k0 < K; k0 += 32) {
        const bool has_next = (k0 + 32 < K);

        // ---- issue next-tile LDGs (latency hidden behind MMAs below) ----
        if (has_next) {
            #pragma unroll
            for (int u = 0; u < 2; u++) {
                pa[u] = *reinterpret_cast<const float4*>(
                    A + (size_t)(m0 + rS[u]) * K + k0 + 32 + kqS[u]);
                pb[u] = *reinterpret_cast<const float4*>(
                    W + (size_t)(n0 + rS[u]) * K + k0 + 32 + kqS[u]);
            }
        }

        // ---- compute on current stage ----
        {
            const uint32_t* As = sm + cur * GEMM_STAGE_U32;
            const uint32_t* Bs = As + 32*132;
            #pragma unroll
            for (int kc = 0; kc < 4; kc++) {
                uint32_t af[2][4];
                #pragma unroll
                for (int mf = 0; mf < 2; mf++) {
                    const uint4 v = *reinterpret_cast<const uint4*>(
                        As + ((wm*2 + mf)*4 + kc) * 132 + lane*4);
                    af[mf][0] = v.x; af[mf][1] = v.y; af[mf][2] = v.z; af[mf][3] = v.w;
                }
                uint32_t bf[4][2];
                #pragma unroll
                for (int nf = 0; nf < 4; nf++) {
                    const uint2 v = *reinterpret_cast<const uint2*>(
                        Bs + ((wn*4 + nf)*4 + kc) * 66 + lane*2);
                    bf[nf][0] = v.x; bf[nf][1] = v.y;
                }
                #pragma unroll
                for (int mf = 0; mf < 2; mf++)
                    #pragma unroll
                    for (int nf = 0; nf < 4; nf++)
                        mma_tf32(acc[mf][nf], af[mf], bf[nf]);
            }
        }

        // ---- convert + store next tile into the other stage ----
        if (has_next) {
            uint32_t* As = sm + (cur ^ 1) * GEMM_STAGE_U32;
            uint32_t* Bs = As + 32*132;
            #pragma unroll
            for (int u = 0; u < 2; u++) {
                const int r = rS[u], kq = kqS[u];
                const int kc = kq >> 3, lo = (kq >> 2) & 1;
                {
                    const int mf = r >> 4, gg = r & 7, hi = (r >> 3) & 1;
                    uint32_t* d = As + (mf*4 + kc) * 132 + gg*16 + (hi + 2*lo);
                    d[0]  = f2tf32(pa[u].x); d[4]  = f2tf32(pa[u].y);
                    d[8]  = f2tf32(pa[u].z); d[12] = f2tf32(pa[u].w);
                }
                {
                    const int nf = r >> 3, gp = r & 7;
                    uint32_t* d = Bs + (nf*4 + kc) * 66 + gp*8 + lo;
                    d[0] = f2tf32(pb[u].x); d[2] = f2tf32(pb[u].y);
                    d[4] = f2tf32(pb[u].z); d[6] = f2tf32(pb[u].w);
                }
            }
        }
        __syncthreads();
        cur ^= 1;
    }

    // ---- epilogue: bias (+relu) (+res), float2 stores ----
    #pragma unroll
    for (int mf = 0; mf < 2; mf++) {
        const int row = m0 + wm*32 + mf*16 + g;
        #pragma unroll
        for (int nf = 0; nf < 4; nf++) {
            const int col = n0 + wn*32 + nf*8 + t*2;
            const float2 bi = *reinterpret_cast<const float2*>(bias + col);
            float2 c0, c1;
            c0.x = acc[mf][nf][0] + bi.x; c0.y = acc[mf][nf][1] + bi.y;
            c1.x = acc[mf][nf][2] + bi.x; c1.y = acc[mf][nf][3] + bi.y;
            if (relu) {
                c0.x = fmaxf(c0.x, 0.f); c0.y = fmaxf(c0.y, 0.f);
                c1.x = fmaxf(c1.x, 0.f); c1.y = fmaxf(c1.y, 0.f);
            }
            const size_t b0 = (size_t)row * N + col;
            const size_t b1 = (size_t)(row + 8) * N + col;
            if (res) {
                const float2 r0 = *reinterpret_cast<const float2*>(res + b0);
                const float2 r1 = *reinterpret_cast<const float2*>(res + b1);
                c0.x += r0.x; c0.y += r0.y;
                c1.x += r1.x; c1.y += r1.y;
            }
            *reinterpret_cast<float2*>(C + b0) = c0;
            *reinterpret_cast<float2*>(C + b1) = c1;
        }
    }
}

// ---------------------------------------------------------------------------
// Tensor-core flash attention (unchanged from passing round 8)
// ---------------------------------------------------------------------------
__global__ __launch_bounds__(128, 2) void attn_tc(
    const float* __restrict__ Q, const float* __restrict__ K,
    const float* __restrict__ V, float* __restrict__ O)
{
    __shared__ uint32_t Vs [64 * 66];   // V fragment-major (k=kv, n=d)
    __shared__ uint32_t KPs[64 * 68];   // union: K frag-major / Qtmp / P row-major

    const int tid  = threadIdx.x;
    const int lane = tid & 31;
    const int w    = tid >> 5;
    const int g    = lane >> 2;
    const int t    = lane & 3;
    const int qb   = blockIdx.x;
    const int bh   = blockIdx.y;
    const int b    = bh >> 4, h = bh & 15;

    const size_t baseQ  = ((size_t)b * SS + (size_t)qb * 64) * DDIM + (size_t)h * DK;
    const size_t baseKV = (size_t)b * SS * DDIM + (size_t)h * DK;

    {
        float* qt = reinterpret_cast<float*>(KPs);
        #pragma unroll
        for (int u = 0; u < 8; u++) {
            const int f = tid + u * 128;
            const int r = f >> 4, cq = (f & 15) << 2;
            *reinterpret_cast<float4*>(qt + r*68 + cq) =
                *reinterpret_cast<const float4*>(Q + baseQ + (size_t)r * DDIM + cq);
        }
    }
    __syncthreads();

    uint32_t aq[8][4];
    {
        const float* qt = reinterpret_cast<const float*>(KPs);
        const int r0 = w*16 + g, r1 = r0 + 8;
        #pragma unroll
        for (int kc = 0; kc < 8; kc++) {
            aq[kc][0] = f2tf32(0.125f * qt[r0*68 + kc*8 + t]);
            aq[kc][1] = f2tf32(0.125f * qt[r1*68 + kc*8 + t]);
            aq[kc][2] = f2tf32(0.125f * qt[r0*68 + kc*8 + t + 4]);
            aq[kc][3] = f2tf32(0.125f * qt[r1*68 + kc*8 + t + 4]);
        }
    }

    float Of[8][4];
    float m0 = -INFINITY, m1 = -INFINITY, l0 = 0.f, l1 = 0.f;
    #pragma unroll
    for (int nf = 0; nf < 8; nf++)
        #pragma unroll
        for (int p = 0; p < 4; p++) Of[nf][p] = 0.f;

    for (int kv0 = 0; kv0 < SS; kv0 += 64) {
        __syncthreads();

        #pragma unroll
        for (int u = 0; u < 8; u++) {
            const int f = tid + u * 128;
            const int r = f >> 4;
            const int kq = (f & 15) << 2;

            {
                float4 kv4 = *reinterpret_cast<const float4*>(
                    K + baseKV + (size_t)(kv0 + r) * DDIM + kq);
                const int kc = kq >> 3, lo = (kq >> 2) & 1;
                const int nf = r >> 3, gp = r & 7;
                uint32_t* d = KPs + (nf*8 + kc) * 66 + gp*8 + lo;
                d[0] = f2tf32(kv4.x);
                d[2] = f2tf32(kv4.y);
                d[4] = f2tf32(kv4.z);
                d[6] = f2tf32(kv4.w);
            }
            {
                float4 vv4 = *reinterpret_cast<const float4*>(
                    V + baseKV + (size_t)(kv0 + r) * DDIM + kq);
                const int kc = r >> 3, kt = r & 7;
                const int tt = kt & 3, e = kt >> 2;
                const int nf = kq >> 3, gn = kq & 7;
                uint32_t* d = Vs + (nf*8 + kc) * 66 + (gn*4 + tt)*2 + e;
                d[0]  = f2tf32(vv4.x);
                d[8]  = f2tf32(vv4.y);
                d[16] = f2tf32(vv4.z);
                d[24] = f2tf32(vv4.w);
            }
        }
        __syncthreads();

        float Sf[8][4];
        #pragma unroll
        for (int nf = 0; nf < 8; nf++)
            #pragma unroll
            for (int p = 0; p < 4; p++) Sf[nf][p] = 0.f;

        #pragma unroll
        for (int kc = 0; kc < 8; kc++) {
            #pragma unroll
            for (int nf = 0; nf < 8; nf++) {
                const uint2 v = *reinterpret_cast<const uint2*>(
                    KPs + (nf*8 + kc) * 66 + lane*2);
                uint32_t bf[2] = { v.x, v.y };
                mma_tf32(Sf[nf], aq[kc], bf);
            }
        }

        float mx0 = -INFINITY, mx1 = -INFINITY;
        #pragma unroll
        for (int nf = 0; nf < 8; nf++) {
            mx0 = fmaxf(mx0, fmaxf(Sf[nf][0], Sf[nf][1]));
            mx1 = fmaxf(mx1, fmaxf(Sf[nf][2], Sf[nf][3]));
        }
        #pragma unroll
        for (int o = 1; o <= 2; o <<= 1) {
            mx0 = fmaxf(mx0, __shfl_xor_sync(0xffffffffu, mx0, o));
            mx1 = fmaxf(mx1, __shfl_xor_sync(0xffffffffu, mx1, o));
        }
        const float mn0 = fmaxf(m0, mx0), mn1 = fmaxf(m1, mx1);
        const float c0 = __expf(m0 - mn0), c1 = __expf(m1 - mn1);
        m0 = mn0; m1 = mn1;

        float s0 = 0.f, s1 = 0.f;
        #pragma unroll
        for (int nf = 0; nf < 8; nf++) {
            float p0 = __expf(Sf[nf][0] - mn0);
            float p1 = __expf(Sf[nf][1] - mn0);
            float p2 = __expf(Sf[nf][2] - mn1);
            float p3 = __expf(Sf[nf][3] - mn1);
            Sf[nf][0] = p0; Sf[nf][1] = p1; Sf[nf][2] = p2; Sf[nf][3] = p3;
            s0 += p0 + p1; s1 += p2 + p3;
        }
        #pragma unroll
        for (int o = 1; o <= 2; o <<= 1) {
            s0 += __shfl_xor_sync(0xffffffffu, s0, o);
            s1 += __shfl_xor_sync(0xffffffffu, s1, o);
        }
        l0 = l0 * c0 + s0;
        l1 = l1 * c1 + s1;
        #pragma unroll
        for (int nf = 0; nf < 8; nf++) {
            Of[nf][0] *= c0; Of[nf][1] *= c0;
            Of[nf][2] *= c1; Of[nf][3] *= c1;
        }

        __syncthreads();
        float* Pw = reinterpret_cast<float*>(KPs) + (w*16) * 68;
        #pragma unroll
        for (int nf = 0; nf < 8; nf++) {
            Pw[g*68     + nf*8 + 2*t    ] = Sf[nf][0];
            Pw[g*68     + nf*8 + 2*t + 1] = Sf[nf][1];
            Pw[(g+8)*68 + nf*8 + 2*t    ] = Sf[nf][2];
            Pw[(g+8)*68 + nf*8 + 2*t + 1] = Sf[nf][3];
        }
        __syncwarp();

        #pragma unroll
        for (int kc = 0; kc < 8; kc++) {
            uint32_t ap[4];
            ap[0] = f2tf32(Pw[g*68     + kc*8 + t    ]);
            ap[1] = f2tf32(Pw[(g+8)*68 + kc*8 + t    ]);
            ap[2] = f2tf32(Pw[g*68     + kc*8 + t + 4]);
            ap[3] = f2tf32(Pw[(g+8)*68 + kc*8 + t + 4]);
            #pragma unroll
            for (int nf = 0; nf < 8; nf++) {
                const uint2 v = *reinterpret_cast<const uint2*>(
                    Vs + (nf*8 + kc) * 66 + lane*2);
                uint32_t bf[2] = { v.x, v.y };
                mma_tf32(Of[nf], ap, bf);
            }
        }
    }

    const float inv0 = 1.0f / l0, inv1 = 1.0f / l1;
    const int r0 = w*16 + g, r1 = r0 + 8;
    #pragma unroll
    for (int nf = 0; nf < 8; nf++) {
        const int col = nf*8 + 2*t;
        float2 o0, o1;
        o0.x = Of[nf][0] * inv0; o0.y = Of[nf][1] * inv0;
        o1.x = Of[nf][2] * inv1; o1.y = Of[nf][3] * inv1;
        *reinterpret_cast<float2*>(O + baseQ + (size_t)r0 * DDIM + col) = o0;
        *reinterpret_cast<float2*>(O + baseQ + (size_t)r1 * DDIM + col) = o1;
    }
}

// ---------------------------------------------------------------------------
// Launch
// ---------------------------------------------------------------------------
extern "C" void kernel_launch(void* const* d_in, const int* in_sizes, int n_in,
                              void* d_out, int out_size)
{
    const float* x    = (const float*)d_in[0];
    const float* wq   = (const float*)d_in[1];
    const float* bq   = (const float*)d_in[2];
    const float* wk   = (const float*)d_in[3];
    const float* bk   = (const float*)d_in[4];
    const float* wv   = (const float*)d_in[5];
    const float* bv   = (const float*)d_in[6];
    const float* wo   = (const float*)d_in[7];
    const float* bo   = (const float*)d_in[8];
    const float* w1   = (const float*)d_in[9];
    const float* b1   = (const float*)d_in[10];
    const float* w2   = (const float*)d_in[11];
    const float* b2   = (const float*)d_in[12];
    const float* ln1a = (const float*)d_in[13];
    const float* ln1b = (const float*)d_in[14];
    const float* ln2a = (const float*)d_in[15];
    const float* ln2b = (const float*)d_in[16];
    float* out = (float*)d_out;

    float *xn, *q, *k, *v, *ctx, *h, *hn, *ff;
    cudaGetSymbolAddress((void**)&xn,  g_xn);
    cudaGetSymbolAddress((void**)&q,   g_q);
    cudaGetSymbolAddress((void**)&k,   g_k);
    cudaGetSymbolAddress((void**)&v,   g_v);
    cudaGetSymbolAddress((void**)&ctx, g_ctx);
    cudaGetSymbolAddress((void**)&h,   g_h);
    cudaGetSymbolAddress((void**)&hn,  g_hn);
    cudaGetSymbolAddress((void**)&ff,  g_ff);

    cudaFuncSetAttribute(gemm_tc,
        cudaFuncAttributeMaxDynamicSharedMemorySize, GEMM_SMEM_BYTES);

    const dim3 gproj(DDIM/128, MTOT/128);   // (8, 32)
    const dim3 gffn1(FFD/128,  MTOT/128);   // (32, 32)

    ln_kernel<<<MTOT, 256>>>(x, ln1a, ln1b, xn);
    gemm_tc<<<gproj, 512, GEMM_SMEM_BYTES>>>(xn, wq, bq, nullptr, q, MTOT, DDIM, DDIM, 0);
    gemm_tc<<<gproj, 512, GEMM_SMEM_BYTES>>>(xn, wk, bk, nullptr, k, MTOT, DDIM, DDIM, 0);
    gemm_tc<<<gproj, 512, GEMM_SMEM_BYTES>>>(xn, wv, bv, nullptr, v, MTOT, DDIM, DDIM, 0);
    attn_tc<<<dim3(SS/64, BB*HH), 128>>>(q, k, v, ctx);
    gemm_tc<<<gproj, 512, GEMM_SMEM_BYTES>>>(ctx, wo, bo, x, h, MTOT, DDIM, DDIM, 0);
    ln_kernel<<<MTOT, 256>>>(h, ln2a, ln2b, hn);
    gemm_tc<<<gffn1, 512, GEMM_SMEM_BYTES>>>(hn, w1, b1, nullptr, ff, MTOT, FFD, DDIM, 1);
    gemm_tc<<<gproj, 512, GEMM_SMEM_BYTES>>>(ff, w2, b2, h, out, MTOT, DDIM, FFD, 0);
}

// round 10
// speedup vs baseline: 1.0049x; 1.0049x over previous
#include <cuda_runtime.h>
#include <math.h>
#include <stdint.h>

// Problem constants
#define BB   2
#define SS   2048
#define DDIM 1024
#define HH   16
#define DK   64
#define FFD  4096
#define MTOT (BB*SS)   // 4096 rows

// ---------------------------------------------------------------------------
// Scratch buffers (device globals; no runtime allocation allowed)
// ---------------------------------------------------------------------------
__device__ float g_xn [MTOT*DDIM];
__device__ float g_q  [MTOT*DDIM];
__device__ float g_k  [MTOT*DDIM];
__device__ float g_v  [MTOT*DDIM];
__device__ float g_ctx[MTOT*DDIM];
__device__ float g_h  [MTOT*DDIM];
__device__ float g_hn [MTOT*DDIM];
__device__ float g_ff [MTOT*FFD];

// ---------------------------------------------------------------------------
// LayerNorm (faithful: unbiased std, denom = sqrt(std + eps))
// ---------------------------------------------------------------------------
__global__ __launch_bounds__(256) void ln_kernel(
    const float* __restrict__ x, const float* __restrict__ alpha,
    const float* __restrict__ beta, float* __restrict__ y)
{
    const int row = blockIdx.x;
    const float4* xr = reinterpret_cast<const float4*>(x + (size_t)row * DDIM);
    float4 vv = xr[threadIdx.x];
    float s  = vv.x + vv.y + vv.z + vv.w;
    float s2 = vv.x*vv.x + vv.y*vv.y + vv.z*vv.z + vv.w*vv.w;

    __shared__ float red0[8], red1[8];
    #pragma unroll
    for (int o = 16; o; o >>= 1) {
        s  += __shfl_xor_sync(0xffffffffu, s,  o);
        s2 += __shfl_xor_sync(0xffffffffu, s2, o);
    }
    const int warp = threadIdx.x >> 5, lane = threadIdx.x & 31;
    if (lane == 0) { red0[warp] = s; red1[warp] = s2; }
    __syncthreads();
    if (threadIdx.x == 0) {
        float t = 0.f, t2 = 0.f;
        #pragma unroll
        for (int i = 0; i < 8; i++) { t += red0[i]; t2 += red1[i]; }
        red0[0] = t; red1[0] = t2;
    }
    __syncthreads();
    s = red0[0]; s2 = red1[0];

    const float mean = s * (1.0f / DDIM);
    const float var  = fmaxf(0.f, (s2 - s * mean) * (1.0f / (DDIM - 1)));  // unbiased
    const float stdv = sqrtf(var);
    const float inv  = 1.0f / sqrtf(stdv + 1e-6f);   // sqrt(std + eps) !
    const float a0 = alpha[0], b0 = beta[0];

    float4 o;
    o.x = a0 * (vv.x - mean) * inv + b0;
    o.y = a0 * (vv.y - mean) * inv + b0;
    o.z = a0 * (vv.z - mean) * inv + b0;
    o.w = a0 * (vv.w - mean) * inv + b0;
    reinterpret_cast<float4*>(y + (size_t)row * DDIM)[threadIdx.x] = o;
}

// ---------------------------------------------------------------------------
// tf32 helpers
// ---------------------------------------------------------------------------
__device__ __forceinline__ uint32_t f2tf32(float x) {
    uint32_t r;
    asm("cvt.rna.tf32.f32 %0, %1;" : "=r"(r) : "f"(x));
    return r;
}

__device__ __forceinline__ void mma_tf32(
    float c[4], const uint32_t a[4], const uint32_t b[2])
{
    asm volatile(
        "mma.sync.aligned.m16n8k8.row.col.f32.tf32.tf32.f32 "
        "{%0,%1,%2,%3}, {%4,%5,%6,%7}, {%8,%9}, {%0,%1,%2,%3};\n"
        : "+f"(c[0]), "+f"(c[1]), "+f"(c[2]), "+f"(c[3])
        : "r"(a[0]), "r"(a[1]), "r"(a[2]), "r"(a[3]), "r"(b[0]), "r"(b[1]));
}

// ---------------------------------------------------------------------------
// Tensor-core GEMM (NT), software-pipelined:
//   C[M,N] = A[M,K]*W[N,K]^T + bias (+relu) (+res)
// 512 threads, warp grid 4(m)x4(n), warp tile 32x32 (2x4 m16n8k8 frags).
// 2-stage smem double buffer (fragment-major layouts from round 7), global
// prefetch into registers overlapped with the MMA phase. K-tile 32.
// Dynamic smem: 2 * (32*132 + 64*66) u32 = 67584 bytes.
// ---------------------------------------------------------------------------
#define GEMM_STAGE_U32 (32*132 + 64*66)   // 8448
#define GEMM_SMEM_BYTES (2 * GEMM_STAGE_U32 * 4)

__global__ __launch_bounds__(512, 1) void gemm_tc(
    const float* __restrict__ A, const float* __restrict__ W,
    const float* __restrict__ bias, const float* __restrict__ res,
    float* __restrict__ C, int M, int N, int K, int relu)
{
    extern __shared__ uint32_t sm[];

    const int tid  = threadIdx.x;
    const int lane = tid & 31;
    const int warp = tid >> 5;          // 0..15
    const int wm = warp >> 2;           // 0..3
    const int wn = warp & 3;            // 0..3
    const int g  = lane >> 2;           // 0..7
    const int t  = lane & 3;            // 0..3
    const int m0 = blockIdx.y * 128, n0 = blockIdx.x * 128;

    // per-thread fill-slot decomposition (2 A slots + 2 B slots)
    int rS[2], kqS[2];
    #pragma unroll
    for (int u = 0; u < 2; u++) {
        const int f = tid + u * 512;    // 0..1023
        rS[u]  = f >> 3;                // 0..127
        kqS[u] = (f & 7) << 2;          // 0..28 step 4
    }

    float acc[2][4][4];
    #pragma unroll
    for (int i = 0; i < 2; i++)
        #pragma unroll
        for (int j = 0; j < 4; j++)
            #pragma unroll
            for (int p = 0; p < 4; p++) acc[i][j][p] = 0.f;

    float4 pa[2], pb[2];

    // ---- prologue: load tile 0, fill stage 0 ----
    #pragma unroll
    for (int u = 0; u < 2; u++) {
        pa[u] = *reinterpret_cast<const float4*>(A + (size_t)(m0 + rS[u]) * K + kqS[u]);
        pb[u] = *reinterpret_cast<const float4*>(W + (size_t)(n0 + rS[u]) * K + kqS[u]);
    }
    {
        uint32_t* As = sm;
        uint32_t* Bs = sm + 32*132;
        #pragma unroll
        for (int u = 0; u < 2; u++) {
            const int r = rS[u], kq = kqS[u];
            const int kc = kq >> 3, lo = (kq >> 2) & 1;
            {   // A
                const int mf = r >> 4, gg = r & 7, hi = (r >> 3) & 1;
                uint32_t* d = As + (mf*4 + kc) * 132 + gg*16 + (hi + 2*lo);
                d[0]  = f2tf32(pa[u].x); d[4]  = f2tf32(pa[u].y);
                d[8]  = f2tf32(pa[u].z); d[12] = f2tf32(pa[u].w);
            }
            {   // B
                const int nf = r >> 3, gp = r & 7;
                uint32_t* d = Bs + (nf*4 + kc) * 66 + gp*8 + lo;
                d[0] = f2tf32(pb[u].x); d[2] = f2tf32(pb[u].y);
                d[4] = f2tf32(pb[u].z); d[6] = f2tf32(pb[u].w);
            }
        }
    }
    __syncthreads();

    int cur = 0;
    for (int k0 = 0; k0 < K; k0 += 32) {
        const bool has_next = (k0 + 32 < K);

        // ---- issue next-tile LDGs (latency hidden behind MMAs below) ----
        if (has_next) {
            #pragma unroll
            for (int u = 0; u < 2; u++) {
                pa[u] = *reinterpret_cast<const float4*>(
                    A + (size_t)(m0 + rS[u]) * K + k0 + 32 + kqS[u]);
                pb[u] = *reinterpret_cast<const float4*>(
                    W + (size_t)(n0 + rS[u]) * K + k0 + 32 + kqS[u]);
            }
        }

        // ---- compute on current stage ----
        {
            const uint32_t* As = sm + cur * GEMM_STAGE_U32;
            const uint32_t* Bs = As + 32*132;
            #pragma unroll
            for (int kc = 0; kc < 4; kc++) {
                uint32_t af[2][4];
                #pragma unroll
                for (int mf = 0; mf < 2; mf++) {
                    const uint4 v = *reinterpret_cast<const uint4*>(
                        As + ((wm*2 + mf)*4 + kc) * 132 + lane*4);
                    af[mf][0] = v.x; af[mf][1] = v.y; af[mf][2] = v.z; af[mf][3] = v.w;
                }
                uint32_t bf[4][2];
                #pragma unroll
                for (int nf = 0; nf < 4; nf++) {
                    const uint2 v = *reinterpret_cast<const uint2*>(
                        Bs + ((wn*4 + nf)*4 + kc) * 66 + lane*2);
                    bf[nf][0] = v.x; bf[nf][1] = v.y;
                }
                #pragma unroll
                for (int mf = 0; mf < 2; mf++)
                    #pragma unroll
                    for (int nf = 0; nf < 4; nf++)
                        mma_tf32(acc[mf][nf], af[mf], bf[nf]);
            }
        }

        // ---- convert + store next tile into the other stage ----
        if (has_next) {
            uint32_t* As = sm + (cur ^ 1) * GEMM_STAGE_U32;
            uint32_t* Bs = As + 32*132;
            #pragma unroll
            for (int u = 0; u < 2; u++) {
                const int r = rS[u], kq = kqS[u];
                const int kc = kq >> 3, lo = (kq >> 2) & 1;
                {
                    const int mf = r >> 4, gg = r & 7, hi = (r >> 3) & 1;
                    uint32_t* d = As + (mf*4 + kc) * 132 + gg*16 + (hi + 2*lo);
                    d[0]  = f2tf32(pa[u].x); d[4]  = f2tf32(pa[u].y);
                    d[8]  = f2tf32(pa[u].z); d[12] = f2tf32(pa[u].w);
                }
                {
                    const int nf = r >> 3, gp = r & 7;
                    uint32_t* d = Bs + (nf*4 + kc) * 66 + gp*8 + lo;
                    d[0] = f2tf32(pb[u].x); d[2] = f2tf32(pb[u].y);
                    d[4] = f2tf32(pb[u].z); d[6] = f2tf32(pb[u].w);
                }
            }
        }
        __syncthreads();
        cur ^= 1;
    }

    // ---- epilogue: bias (+relu) (+res), float2 stores ----
    #pragma unroll
    for (int mf = 0; mf < 2; mf++) {
        const int row = m0 + wm*32 + mf*16 + g;
        #pragma unroll
        for (int nf = 0; nf < 4; nf++) {
            const int col = n0 + wn*32 + nf*8 + t*2;
            const float2 bi = *reinterpret_cast<const float2*>(bias + col);
            float2 c0, c1;
            c0.x = acc[mf][nf][0] + bi.x; c0.y = acc[mf][nf][1] + bi.y;
            c1.x = acc[mf][nf][2] + bi.x; c1.y = acc[mf][nf][3] + bi.y;
            if (relu) {
                c0.x = fmaxf(c0.x, 0.f); c0.y = fmaxf(c0.y, 0.f);
                c1.x = fmaxf(c1.x, 0.f); c1.y = fmaxf(c1.y, 0.f);
            }
            const size_t b0 = (size_t)row * N + col;
            const size_t b1 = (size_t)(row + 8) * N + col;
            if (res) {
                const float2 r0 = *reinterpret_cast<const float2*>(res + b0);
                const float2 r1 = *reinterpret_cast<const float2*>(res + b1);
                c0.x += r0.x; c0.y += r0.y;
                c1.x += r1.x; c1.y += r1.y;
            }
            *reinterpret_cast<float2*>(C + b0) = c0;
            *reinterpret_cast<float2*>(C + b1) = c1;
        }
    }
}

// ---------------------------------------------------------------------------
// Tensor-core flash attention (unchanged from passing round 8)
// ---------------------------------------------------------------------------
__global__ __launch_bounds__(128, 2) void attn_tc(
    const float* __restrict__ Q, const float* __restrict__ K,
    const float* __restrict__ V, float* __restrict__ O)
{
    __shared__ uint32_t Vs [64 * 66];   // V fragment-major (k=kv, n=d)
    __shared__ uint32_t KPs[64 * 68];   // union: K frag-major / Qtmp / P row-major

    const int tid  = threadIdx.x;
    const int lane = tid & 31;
    const int w    = tid >> 5;
    const int g    = lane >> 2;
    const int t    = lane & 3;
    const int qb   = blockIdx.x;
    const int bh   = blockIdx.y;
    const int b    = bh >> 4, h = bh & 15;

    const size_t baseQ  = ((size_t)b * SS + (size_t)qb * 64) * DDIM + (size_t)h * DK;
    const size_t baseKV = (size_t)b * SS * DDIM + (size_t)h * DK;

    {
        float* qt = reinterpret_cast<float*>(KPs);
        #pragma unroll
        for (int u = 0; u < 8; u++) {
            const int f = tid + u * 128;
            const int r = f >> 4, cq = (f & 15) << 2;
            *reinterpret_cast<float4*>(qt + r*68 + cq) =
                *reinterpret_cast<const float4*>(Q + baseQ + (size_t)r * DDIM + cq);
        }
    }
    __syncthreads();

    uint32_t aq[8][4];
    {
        const float* qt = reinterpret_cast<const float*>(KPs);
        const int r0 = w*16 + g, r1 = r0 + 8;
        #pragma unroll
        for (int kc = 0; kc < 8; kc++) {
            aq[kc][0] = f2tf32(0.125f * qt[r0*68 + kc*8 + t]);
            aq[kc][1] = f2tf32(0.125f * qt[r1*68 + kc*8 + t]);
            aq[kc][2] = f2tf32(0.125f * qt[r0*68 + kc*8 + t + 4]);
            aq[kc][3] = f2tf32(0.125f * qt[r1*68 + kc*8 + t + 4]);
        }
    }

    float Of[8][4];
    float m0 = -INFINITY, m1 = -INFINITY, l0 = 0.f, l1 = 0.f;
    #pragma unroll
    for (int nf = 0; nf < 8; nf++)
        #pragma unroll
        for (int p = 0; p < 4; p++) Of[nf][p] = 0.f;

    for (int kv0 = 0; kv0 < SS; kv0 += 64) {
        __syncthreads();

        #pragma unroll
        for (int u = 0; u < 8; u++) {
            const int f = tid + u * 128;
            const int r = f >> 4;
            const int kq = (f & 15) << 2;

            {
                float4 kv4 = *reinterpret_cast<const float4*>(
                    K + baseKV + (size_t)(kv0 + r) * DDIM + kq);
                const int kc = kq >> 3, lo = (kq >> 2) & 1;
                const int nf = r >> 3, gp = r & 7;
                uint32_t* d = KPs + (nf*8 + kc) * 66 + gp*8 + lo;
                d[0] = f2tf32(kv4.x);
                d[2] = f2tf32(kv4.y);
                d[4] = f2tf32(kv4.z);
                d[6] = f2tf32(kv4.w);
            }
            {
                float4 vv4 = *reinterpret_cast<const float4*>(
                    V + baseKV + (size_t)(kv0 + r) * DDIM + kq);
                const int kc = r >> 3, kt = r & 7;
                const int tt = kt & 3, e = kt >> 2;
                const int nf = kq >> 3, gn = kq & 7;
                uint32_t* d = Vs + (nf*8 + kc) * 66 + (gn*4 + tt)*2 + e;
                d[0]  = f2tf32(vv4.x);
                d[8]  = f2tf32(vv4.y);
                d[16] = f2tf32(vv4.z);
                d[24] = f2tf32(vv4.w);
            }
        }
        __syncthreads();

        float Sf[8][4];
        #pragma unroll
        for (int nf = 0; nf < 8; nf++)
            #pragma unroll
            for (int p = 0; p < 4; p++) Sf[nf][p] = 0.f;

        #pragma unroll
        for (int kc = 0; kc < 8; kc++) {
            #pragma unroll
            for (int nf = 0; nf < 8; nf++) {
                const uint2 v = *reinterpret_cast<const uint2*>(
                    KPs + (nf*8 + kc) * 66 + lane*2);
                uint32_t bf[2] = { v.x, v.y };
                mma_tf32(Sf[nf], aq[kc], bf);
            }
        }

        float mx0 = -INFINITY, mx1 = -INFINITY;
        #pragma unroll
        for (int nf = 0; nf < 8; nf++) {
            mx0 = fmaxf(mx0, fmaxf(Sf[nf][0], Sf[nf][1]));
            mx1 = fmaxf(mx1, fmaxf(Sf[nf][2], Sf[nf][3]));
        }
        #pragma unroll
        for (int o = 1; o <= 2; o <<= 1) {
            mx0 = fmaxf(mx0, __shfl_xor_sync(0xffffffffu, mx0, o));
            mx1 = fmaxf(mx1, __shfl_xor_sync(0xffffffffu, mx1, o));
        }
        const float mn0 = fmaxf(m0, mx0), mn1 = fmaxf(m1, mx1);
        const float c0 = __expf(m0 - mn0), c1 = __expf(m1 - mn1);
        m0 = mn0; m1 = mn1;

        float s0 = 0.f, s1 = 0.f;
        #pragma unroll
        for (int nf = 0; nf < 8; nf++) {
            float p0 = __expf(Sf[nf][0] - mn0);
            float p1 = __expf(Sf[nf][1] - mn0);
            float p2 = __expf(Sf[nf][2] - mn1);
            float p3 = __expf(Sf[nf][3] - mn1);
            Sf[nf][0] = p0; Sf[nf][1] = p1; Sf[nf][2] = p2; Sf[nf][3] = p3;
            s0 += p0 + p1; s1 += p2 + p3;
        }
        #pragma unroll
        for (int o = 1; o <= 2; o <<= 1) {
            s0 += __shfl_xor_sync(0xffffffffu, s0, o);
            s1 += __shfl_xor_sync(0xffffffffu, s1, o);
        }
        l0 = l0 * c0 + s0;
        l1 = l1 * c1 + s1;
        #pragma unroll
        for (int nf = 0; nf < 8; nf++) {
            Of[nf][0] *= c0; Of[nf][1] *= c0;
            Of[nf][2] *= c1; Of[nf][3] *= c1;
        }

        __syncthreads();
        float* Pw = reinterpret_cast<float*>(KPs) + (w*16) * 68;
        #pragma unroll
        for (int nf = 0; nf < 8; nf++) {
            Pw[g*68     + nf*8 + 2*t    ] = Sf[nf][0];
            Pw[g*68     + nf*8 + 2*t + 1] = Sf[nf][1];
            Pw[(g+8)*68 + nf*8 + 2*t    ] = Sf[nf][2];
            Pw[(g+8)*68 + nf*8 + 2*t + 1] = Sf[nf][3];
        }
        __syncwarp();

        #pragma unroll
        for (int kc = 0; kc < 8; kc++) {
            uint32_t ap[4];
            ap[0] = f2tf32(Pw[g*68     + kc*8 + t    ]);
            ap[1] = f2tf32(Pw[(g+8)*68 + kc*8 + t    ]);
            ap[2] = f2tf32(Pw[g*68     + kc*8 + t + 4]);
            ap[3] = f2tf32(Pw[(g+8)*68 + kc*8 + t + 4]);
            #pragma unroll
            for (int nf = 0; nf < 8; nf++) {
                const uint2 v = *reinterpret_cast<const uint2*>(
                    Vs + (nf*8 + kc) * 66 + lane*2);
                uint32_t bf[2] = { v.x, v.y };
                mma_tf32(Of[nf], ap, bf);
            }
        }
    }

    const float inv0 = 1.0f / l0, inv1 = 1.0f / l1;
    const int r0 = w*16 + g, r1 = r0 + 8;
    #pragma unroll
    for (int nf = 0; nf < 8; nf++) {
        const int col = nf*8 + 2*t;
        float2 o0, o1;
        o0.x = Of[nf][0] * inv0; o0.y = Of[nf][1] * inv0;
        o1.x = Of[nf][2] * inv1; o1.y = Of[nf][3] * inv1;
        *reinterpret_cast<float2*>(O + baseQ + (size_t)r0 * DDIM + col) = o0;
        *reinterpret_cast<float2*>(O + baseQ + (size_t)r1 * DDIM + col) = o1;
    }
}

// ---------------------------------------------------------------------------
// Launch
// ---------------------------------------------------------------------------
extern "C" void kernel_launch(void* const* d_in, const int* in_sizes, int n_in,
                              void* d_out, int out_size)
{
    const float* x    = (const float*)d_in[0];
    const float* wq   = (const float*)d_in[1];
    const float* bq   = (const float*)d_in[2];
    const float* wk   = (const float*)d_in[3];
    const float* bk   = (const float*)d_in[4];
    const float* wv   = (const float*)d_in[5];
    const float* bv   = (const float*)d_in[6];
    const float* wo   = (const float*)d_in[7];
    const float* bo   = (const float*)d_in[8];
    const float* w1   = (const float*)d_in[9];
    const float* b1   = (const float*)d_in[10];
    const float* w2   = (const float*)d_in[11];
    const float* b2   = (const float*)d_in[12];
    const float* ln1a = (const float*)d_in[13];
    const float* ln1b = (const float*)d_in[14];
    const float* ln2a = (const float*)d_in[15];
    const float* ln2b = (const float*)d_in[16];
    float* out = (float*)d_out;

    float *xn, *q, *k, *v, *ctx, *h, *hn, *ff;
    cudaGetSymbolAddress((void**)&xn,  g_xn);
    cudaGetSymbolAddress((void**)&q,   g_q);
    cudaGetSymbolAddress((void**)&k,   g_k);
    cudaGetSymbolAddress((void**)&v,   g_v);
    cudaGetSymbolAddress((void**)&ctx, g_ctx);
    cudaGetSymbolAddress((void**)&h,   g_h);
    cudaGetSymbolAddress((void**)&hn,  g_hn);
    cudaGetSymbolAddress((void**)&ff,  g_ff);

    cudaFuncSetAttribute(gemm_tc,
        cudaFuncAttributeMaxDynamicSharedMemorySize, GEMM_SMEM_BYTES);

    const dim3 gproj(DDIM/128, MTOT/128);   // (8, 32)
    const dim3 gffn1(FFD/128,  MTOT/128);   // (32, 32)

    ln_kernel<<<MTOT, 256>>>(x, ln1a, ln1b, xn);
    gemm_tc<<<gproj, 512, GEMM_SMEM_BYTES>>>(xn, wq, bq, nullptr, q, MTOT, DDIM, DDIM, 0);
    gemm_tc<<<gproj, 512, GEMM_SMEM_BYTES>>>(xn, wk, bk, nullptr, k, MTOT, DDIM, DDIM, 0);
    gemm_tc<<<gproj, 512, GEMM_SMEM_BYTES>>>(xn, wv, bv, nullptr, v, MTOT, DDIM, DDIM, 0);
    attn_tc<<<dim3(SS/64, BB*HH), 128>>>(q, k, v, ctx);
    gemm_tc<<<gproj, 512, GEMM_SMEM_BYTES>>>(ctx, wo, bo, x, h, MTOT, DDIM, DDIM, 0);
    ln_kernel<<<MTOT, 256>>>(h, ln2a, ln2b, hn);
    gemm_tc<<<gffn1, 512, GEMM_SMEM_BYTES>>>(hn, w1, b1, nullptr, ff, MTOT, FFD, DDIM, 1);
    gemm_tc<<<gproj, 512, GEMM_SMEM_BYTES>>>(ff, w2, b2, h, out, MTOT, DDIM, FFD, 0);
}